// round 1
// baseline (speedup 1.0000x reference)
#include <cuda_runtime.h>

// QuantumLayer: B=512, Q=14, L=2.
// Closed-form Heisenberg evaluation:
//   outs[b,i] = <s0| C^T R^T C^T Z_i C R C |s0>
// with s0 = prod-state from angles theta_q = x[b,q]+w0[q],
// C = adjacent CNOT chain (Clifford), R = tensor RY(w1_j).
// Pauli propagation: C^T Z_i C = Z_0..Z_i ; R^T Z_j R = cos(w1_j) Z - sin(w1_j) X ;
// C^T Z_j C = Z_0..Z_j ; C^T X_j C = X_j X_{j+1} (X_{Q-1} -> X_{Q-1}).
// Product-state expectations: <Z_q>=cos(theta_q), <X_q>=sin(theta_q), <Y_q>=0.
// Y-collision terms vanish; all survivors have sign +1 (verified by per-qubit
// case analysis). The 2^(i+1)-term sum reduces to a 3-state DP over t=i..0:
//   state s[p][x], p = parity of Z-choices so far, x = last choice was X.
//   (p=1,x=1) is unreachable -> 3 live states.

#define QN 14
#define BN 512

__global__ void __launch_bounds__(32)
quantum_dp_kernel(const float* __restrict__ x,
                  const float* __restrict__ w,
                  float* __restrict__ out)
{
    __shared__ float Cq[QN], Sq[QN], Az[QN], Ax[QN];

    const int b = blockIdx.x;
    const int i = threadIdx.x;

    if (i < QN) {
        // theta_q = x[b,q] + weights[0,q]  (RY angles compose on same axis)
        float th = x[b * QN + i] + w[i];
        float s, c;
        sincosf(th, &s, &c);
        Cq[i] = c;          // <Z_q>
        Sq[i] = s;          // <X_q>
        float w1 = w[QN + i];
        float s1, c1;
        sincosf(w1, &s1, &c1);
        Az[i] = c1;         // coeff for Z-choice at t
        Ax[i] = -s1;        // coeff for X-choice at t
    }
    __syncthreads();

    if (i < QN) {
        // init at t = i: sigma=Z -> (p=1,x=0), sigma=X -> (p=0,x=1) with tail
        // factor S_{i+1} from X_i -> X_i X_{i+1} (no tail when i = Q-1).
        float tail = (i < QN - 1) ? Sq[i + 1] : 1.0f;
        float s00 = 0.0f;           // (p=0, x=0)
        float s10 = Az[i];          // (p=1, x=0)
        float s01 = Ax[i] * tail;   // (p=0, x=1)

        // descend t = i-1 .. 0; at step t emit the factor for qubit t+1:
        //   Xs = x_old XOR (sigma==X); factor = Xs ? (p?0:S_{t+1}) : (p?C_{t+1}:1)
        #pragma unroll
        for (int t = QN - 2; t >= 0; --t) {
            if (t > i - 1) continue;   // uniform unroll, active range t<=i-1
            float cz = Az[t], cx = Ax[t];
            float fC = Cq[t + 1], fS = Sq[t + 1];
            // sigma=Z: new x=0, p flips
            float n10 = cz * fmaf(fS, s01, s00);  // from (0,0)&(0,1)
            float n00 = cz * fC * s10;            // from (1,0); (1,1) dead
            // sigma=X: new x=1, p keeps
            float n01 = cx * fmaf(fS, s00, s01);  // from (0,0)&(0,1)
            s00 = n00;
            s01 = n01;
            s10 = n10;
        }

        // final emit for qubit 0 (xprev = 0):
        // (0,0)->1, (1,0)->C_0, (0,1)->S_0
        out[b * QN + i] = s00 + Cq[0] * s10 + Sq[0] * s01;
    }
}

extern "C" void kernel_launch(void* const* d_in, const int* in_sizes, int n_in,
                              void* d_out, int out_size)
{
    const float* x = (const float*)d_in[0];   // [512, 14]
    const float* w = (const float*)d_in[1];   // [2, 14]
    float* out = (float*)d_out;               // [512, 14]

    quantum_dp_kernel<<<BN, 32>>>(x, w, out);
}

// round 2
// speedup vs baseline: 1.0047x; 1.0047x over previous
#include <cuda_runtime.h>

// QuantumLayer: B=512, Q=14, L=2.
// Closed-form Heisenberg evaluation (see R1 derivation):
//   outs[b,i] = <s0| C^T R^T C^T Z_i C R C |s0>
// reduced to a 3-state linear DP over qubits. This round: shuffle-based
// (no smem, no barriers), 16 lanes per batch, 32 CTAs x 256 threads.

#define QN 14
#define BN 512

__global__ void __launch_bounds__(256)
quantum_dp_kernel(const float* __restrict__ x,
                  const float* __restrict__ w,
                  float* __restrict__ out)
{
    const int tid = blockIdx.x * blockDim.x + threadIdx.x;
    const int b = tid >> 4;        // 16 lanes per batch
    const int i = tid & 15;        // lane i owns qubit i (i>=14 inactive)

    // Lane-local table entries for qubit i of batch b.
    float Cq = 1.0f, Sq = 0.0f, Az = 1.0f, Ax = 0.0f;
    if (i < QN) {
        float th = __ldg(&x[b * QN + i]) + __ldg(&w[i]);   // angles compose
        float s, c;
        sincosf(th, &s, &c);
        Cq = c;            // <Z_i>
        Sq = s;            // <X_i>
        float w1 = __ldg(&w[QN + i]);
        float s1, c1;
        sincosf(w1, &s1, &c1);
        Az = c1;           // Z-choice coeff
        Ax = -s1;          // X-choice coeff
    }

    const unsigned m = 0xFFFFFFFFu;

    // tail = Sq[i+1] (1.0 when i == Q-1); lane-varying source -> shfl_down
    float Sq_next = __shfl_down_sync(m, Sq, 1, 16);
    float tail = (i < QN - 1) ? Sq_next : 1.0f;

    // DP state: (p = Z-parity, x = last-was-X); (1,1) unreachable.
    float s00 = 0.0f;          // (0,0)
    float s10 = Az;            // (1,0)
    float s01 = Ax * tail;     // (0,1)

    // Descend t = i-1 .. 0. Shuffle sources are uniform per iteration
    // (broadcast) and independent of the DP chain -> fully pipelined.
    #pragma unroll
    for (int t = QN - 2; t >= 0; --t) {
        float cz = __shfl_sync(m, Az, t,     16);
        float cx = __shfl_sync(m, Ax, t,     16);
        float fC = __shfl_sync(m, Cq, t + 1, 16);
        float fS = __shfl_sync(m, Sq, t + 1, 16);
        if (t <= i - 1) {
            float n10 = cz * fmaf(fS, s01, s00);   // sigma=Z: p flips, x=0
            float n00 = cz * fC * s10;             // from (1,0)
            float n01 = cx * fmaf(fS, s00, s01);   // sigma=X: p keeps, x=1
            s00 = n00;
            s01 = n01;
            s10 = n10;
        }
    }

    // Final emit for qubit 0: (0,0)->1, (1,0)->Cq[0], (0,1)->Sq[0]
    float C0 = __shfl_sync(m, Cq, 0, 16);
    float S0 = __shfl_sync(m, Sq, 0, 16);
    if (i < QN)
        out[b * QN + i] = fmaf(C0, s10, fmaf(S0, s01, s00));
}

extern "C" void kernel_launch(void* const* d_in, const int* in_sizes, int n_in,
                              void* d_out, int out_size)
{
    const float* x = (const float*)d_in[0];   // [512, 14]
    const float* w = (const float*)d_in[1];   // [2, 14]
    float* out = (float*)d_out;               // [512, 14]

    // 512 batches * 16 lanes = 8192 threads = 32 CTAs x 256
    quantum_dp_kernel<<<(BN * 16) / 256, 256>>>(x, w, out);
}

// round 3
// speedup vs baseline: 1.1134x; 1.1082x over previous
#include <cuda_runtime.h>

// QuantumLayer: B=512, Q=14, L=2.
// Closed-form Heisenberg evaluation (see R1 derivation):
//   outs[b,i] = <s0| C^T R^T C^T Z_i C R C |s0>
// reduced to a 3-state linear DP over qubits. Shuffle-based (no smem, no
// barriers), 16 lanes per batch. This round: __sincosf fast intrinsic
// (inputs |th| < ~6, well inside accuracy budget) and a 128x64 launch
// (2 warps x 128 SMs, single wave, minimal per-SM serialization).

#define QN 14
#define BN 512

__global__ void __launch_bounds__(64)
quantum_dp_kernel(const float* __restrict__ x,
                  const float* __restrict__ w,
                  float* __restrict__ out)
{
    const int tid = blockIdx.x * blockDim.x + threadIdx.x;
    const int b = tid >> 4;        // 16 lanes per batch
    const int i = tid & 15;        // lane i owns qubit i (i>=14 inactive)

    // Lane-local table entries for qubit i of batch b.
    float Cq = 1.0f, Sq = 0.0f, Az = 1.0f, Ax = 0.0f;
    if (i < QN) {
        float th = __ldg(&x[b * QN + i]) + __ldg(&w[i]);   // angles compose
        float s, c;
        __sincosf(th, &s, &c);      // fast MUFU path, no range-reduction branches
        Cq = c;            // <Z_i>
        Sq = s;            // <X_i>
        float w1 = __ldg(&w[QN + i]);
        float s1, c1;
        __sincosf(w1, &s1, &c1);
        Az = c1;           // Z-choice coeff
        Ax = -s1;          // X-choice coeff
    }

    const unsigned m = 0xFFFFFFFFu;

    // tail = Sq[i+1] (1.0 when i == Q-1); lane-varying source -> shfl_down
    float Sq_next = __shfl_down_sync(m, Sq, 1, 16);
    float tail = (i < QN - 1) ? Sq_next : 1.0f;

    // DP state: (p = Z-parity, x = last-was-X); (1,1) unreachable.
    float s00 = 0.0f;          // (0,0)
    float s10 = Az;            // (1,0)
    float s01 = Ax * tail;     // (0,1)

    // Descend t = i-1 .. 0. Shuffle sources are uniform per iteration
    // (broadcast) and independent of the DP chain -> fully pipelined.
    #pragma unroll
    for (int t = QN - 2; t >= 0; --t) {
        float cz = __shfl_sync(m, Az, t,     16);
        float cx = __shfl_sync(m, Ax, t,     16);
        float fC = __shfl_sync(m, Cq, t + 1, 16);
        float fS = __shfl_sync(m, Sq, t + 1, 16);
        if (t <= i - 1) {
            float n10 = cz * fmaf(fS, s01, s00);   // sigma=Z: p flips, x=0
            float n00 = cz * fC * s10;             // from (1,0)
            float n01 = cx * fmaf(fS, s00, s01);   // sigma=X: p keeps, x=1
            s00 = n00;
            s01 = n01;
            s10 = n10;
        }
    }

    // Final emit for qubit 0: (0,0)->1, (1,0)->Cq[0], (0,1)->Sq[0]
    float C0 = __shfl_sync(m, Cq, 0, 16);
    float S0 = __shfl_sync(m, Sq, 0, 16);
    if (i < QN)
        out[b * QN + i] = fmaf(C0, s10, fmaf(S0, s01, s00));
}

extern "C" void kernel_launch(void* const* d_in, const int* in_sizes, int n_in,
                              void* d_out, int out_size)
{
    const float* x = (const float*)d_in[0];   // [512, 14]
    const float* w = (const float*)d_in[1];   // [2, 14]
    float* out = (float*)d_out;               // [512, 14]

    // 512 batches * 16 lanes = 8192 threads = 128 CTAs x 64 (single wave)
    quantum_dp_kernel<<<(BN * 16) / 64, 64>>>(x, w, out);
}

// round 4
// speedup vs baseline: 1.4795x; 1.3288x over previous
#include <cuda_runtime.h>

// QuantumLayer: B=512, Q=14, L=2.
// Closed-form Heisenberg evaluation (see R1 derivation):
//   outs[b,i] = <s0| C^T R^T C^T Z_i C R C |s0>
// reduced to a 3-state linear DP over qubits. Shuffle-based, no smem, no
// barriers, 16 lanes per batch (2 batches per warp).
// This round: 256 CTAs x 32 threads (single-warp CTAs, zero intra-CTA skew,
// all resident in one wave), tail factor taken from the broadcast shuffle
// set, emit shuffles hoisted ahead of the DP chain.

#define QN 14
#define BN 512

__global__ void __launch_bounds__(32)
quantum_dp_kernel(const float* __restrict__ x,
                  const float* __restrict__ w,
                  float* __restrict__ out)
{
    const int tid = blockIdx.x * 32 + threadIdx.x;
    const int b = tid >> 4;        // 16 lanes per batch
    const int i = tid & 15;        // lane i owns qubit i (i>=14 inactive)

    // Lane-local table entries for qubit i of batch b.
    float Cq = 1.0f, Sq = 0.0f, Az = 1.0f, Ax = 0.0f;
    if (i < QN) {
        float th = __ldg(&x[b * QN + i]) + __ldg(&w[i]);   // angles compose
        float s, c;
        __sincosf(th, &s, &c);      // fast MUFU path
        Cq = c;            // <Z_i>
        Sq = s;            // <X_i>
        float w1 = __ldg(&w[QN + i]);
        float s1, c1;
        __sincosf(w1, &s1, &c1);
        Az = c1;           // Z-choice coeff
        Ax = -s1;          // X-choice coeff
    }

    const unsigned m = 0xFFFFFFFFu;

    // Emit factors (qubit 0) — issued early, independent of the DP chain.
    float C0 = __shfl_sync(m, Cq, 0, 16);
    float S0 = __shfl_sync(m, Sq, 0, 16);

    // tail = Sq[i+1] (1.0 when i == Q-1); lane-varying source.
    float Sq_next = __shfl_down_sync(m, Sq, 1, 16);
    float tail = (i < QN - 1) ? Sq_next : 1.0f;

    // DP state: (p = Z-parity, x = last-was-X); (1,1) unreachable.
    float s00 = 0.0f;          // (0,0)
    float s10 = Az;            // (1,0)
    float s01 = Ax * tail;     // (0,1)

    // Descend t = i-1 .. 0. Shuffle sources are uniform per iteration
    // (broadcast) and independent of the DP chain -> fully pipelined.
    #pragma unroll
    for (int t = QN - 2; t >= 0; --t) {
        float cz = __shfl_sync(m, Az, t,     16);
        float cx = __shfl_sync(m, Ax, t,     16);
        float fC = __shfl_sync(m, Cq, t + 1, 16);
        float fS = __shfl_sync(m, Sq, t + 1, 16);
        if (t <= i - 1) {
            float n10 = cz * fmaf(fS, s01, s00);   // sigma=Z: p flips, x=0
            float n00 = cz * fC * s10;             // from (1,0)
            float n01 = cx * fmaf(fS, s00, s01);   // sigma=X: p keeps, x=1
            s00 = n00;
            s01 = n01;
            s10 = n10;
        }
    }

    // Final emit for qubit 0: (0,0)->1, (1,0)->Cq[0], (0,1)->Sq[0]
    if (i < QN)
        out[b * QN + i] = fmaf(C0, s10, fmaf(S0, s01, s00));
}

extern "C" void kernel_launch(void* const* d_in, const int* in_sizes, int n_in,
                              void* d_out, int out_size)
{
    const float* x = (const float*)d_in[0];   // [512, 14]
    const float* w = (const float*)d_in[1];   // [2, 14]
    float* out = (float*)d_out;               // [512, 14]

    // 512 batches * 16 lanes = 8192 threads = 256 CTAs x 32 (all resident)
    quantum_dp_kernel<<<(BN * 16) / 32, 32>>>(x, w, out);
}